// round 15
// baseline (speedup 1.0000x reference)
#include <cuda_runtime.h>

typedef unsigned long long u64;
typedef unsigned int u32;

#define TPB   128
#define EPW   4                     // elements per warp
#define EPB   16                    // elements per block
#define TROW  32                    // words per t-row
#define IMG   904                   // 28*32 + 8 skew; 904%32=8 -> elem quads disjoint
#define XW    (EPB * IMG)           // 14464 words
#define SMEMW (XW + 64)             // pad covers t=28 pipeline prefetch

// byte-LUT in gmem (L1D-cached): [p4][byte][j], j stride 10 (R13-proven)
__device__ float g_lut[4 * 256 * 10];

// ---- packed fp32x2 helpers (sm_103a dual-fp32: 2x FFMA throughput) ----
__device__ __forceinline__ u64 pk(float lo, float hi) {
    u64 r; asm("mov.b64 %0, {%1, %2};" : "=l"(r) : "f"(lo), "f"(hi)); return r;
}
__device__ __forceinline__ void upk(float& lo, float& hi, u64 v) {
    asm("mov.b64 {%0, %1}, %2;" : "=f"(lo), "=f"(hi) : "l"(v));
}
__device__ __forceinline__ u64 fma2(u64 a, u64 b, u64 c) {
    u64 d; asm("fma.rn.f32x2 %0, %1, %2, %3;" : "=l"(d) : "l"(a), "l"(b), "l"(c)); return d;
}
__device__ __forceinline__ u64 add2(u64 a, u64 b) {
    u64 d; asm("add.rn.f32x2 %0, %1, %2;" : "=l"(d) : "l"(a), "l"(b)); return d;
}

// layer-1 for timestep tt: i-pair packed lanes. acc_u = (b+Σ_even x_i w_i, Σ_odd),
// h_u = lo+hi. x pairs come straight from the LDS.128 quad: ZERO pack MOVs.
#define COMPUTE_H(tt, H0, H1, H2, H3)                                           \
    do {                                                                        \
        const ulonglong2* xr_ =                                                 \
            reinterpret_cast<const ulonglong2*>(xbase + (tt) * TROW);           \
        u64 a0 = hb0, a1 = hb1, a2 = hb2, a3 = hb3;                             \
        _Pragma("unroll")                                                       \
        for (int k = 0; k < 7; ++k) {                                           \
            ulonglong2 xp = xr_[k];            /* (x4k,x4k+1),(x4k+2,x4k+3) */  \
            a0 = fma2(xp.x, w0[2 * k], a0);                                     \
            a1 = fma2(xp.x, w1[2 * k], a1);                                     \
            a2 = fma2(xp.x, w2[2 * k], a2);                                     \
            a3 = fma2(xp.x, w3[2 * k], a3);                                     \
            a0 = fma2(xp.y, w0[2 * k + 1], a0);                                 \
            a1 = fma2(xp.y, w1[2 * k + 1], a1);                                 \
            a2 = fma2(xp.y, w2[2 * k + 1], a2);                                 \
            a3 = fma2(xp.y, w3[2 * k + 1], a3);                                 \
        }                                                                       \
        { float lo_, hi_;                                                       \
          upk(lo_, hi_, a0); (H0) = lo_ + hi_;                                  \
          upk(lo_, hi_, a1); (H1) = lo_ + hi_;                                  \
          upk(lo_, hi_, a2); (H2) = lo_ + hi_;                                  \
          upk(lo_, hi_, a3); (H3) = lo_ + hi_; }                                \
    } while (0)

// ======== prologue kernel: build byte-LUT (R13's exact fp order) ========
__global__ void build_lut(const float* __restrict__ W2)
{
    int idx = blockIdx.x * blockDim.x + threadIdx.x;
    if (idx < 4 * 256 * 10) {
        int j  = idx % 10;
        int vv = (idx / 10) & 255;
        int p4 = idx / 2560;
        float slo = 0.0f, shi = 0.0f;
#pragma unroll
        for (int bb = 0; bb < 4; ++bb)
            if ((vv >> bb) & 1) slo += W2[j * 32 + 8 * p4 + bb];
#pragma unroll
        for (int bb = 0; bb < 4; ++bb)
            if ((vv >> (4 + bb)) & 1) shi += W2[j * 32 + 8 * p4 + 4 + bb];
        g_lut[idx] = slo + shi;
    }
}

extern __shared__ __align__(16) float smem_f[];

__global__ void __launch_bounds__(TPB, 3) snn_kernel(
    const float* __restrict__ x,  const float* __restrict__ W1,
    const float* __restrict__ b1, const float* __restrict__ W2,
    const float* __restrict__ b2, float* __restrict__ out, int B)
{
    float* smx = smem_f;            // staged x, t-major rows

    const int tid = threadIdx.x;
    const int lid = tid & 31;
    const int wid = tid >> 5;
    const int q   = lid >> 3;       // elem within warp (0..3)
    const int r   = lid & 7;        // unit-slice: owns units r, r+8, r+16, r+24
    const int eLocal = wid * EPW + q;
    const int gbase  = blockIdx.x * EPB;

    // ======== stage x: [e][t][i] rows (float4 LDG, scalar STS) ========
    for (int task = tid; task < EPB * 28; task += TPB) {
        int e = task / 28, i = task - e * 28;
        if (gbase + e < B) {
            const float4* src = reinterpret_cast<const float4*>(
                x + (size_t)(gbase + e) * 784 + i * 28);
            float* dst = smx + e * IMG + i;
#pragma unroll
            for (int c = 0; c < 7; ++c) {
                float4 v4 = __ldg(src + c);
                dst[(4 * c + 0) * TROW] = v4.x;
                dst[(4 * c + 1) * TROW] = v4.y;
                dst[(4 * c + 2) * TROW] = v4.z;
                dst[(4 * c + 3) * TROW] = v4.w;
            }
        }
    }

    // ======== per-lane weights, i-pair packed: w_u[m] = (W1[u][2m], W1[u][2m+1]) ====
    u64 w0[14], w1[14], w2[14], w3[14];
    {
        const ulonglong2* q0 = reinterpret_cast<const ulonglong2*>(W1 + r * 28);
        const ulonglong2* q1 = reinterpret_cast<const ulonglong2*>(W1 + (r + 8) * 28);
        const ulonglong2* q2 = reinterpret_cast<const ulonglong2*>(W1 + (r + 16) * 28);
        const ulonglong2* q3 = reinterpret_cast<const ulonglong2*>(W1 + (r + 24) * 28);
#pragma unroll
        for (int c = 0; c < 7; ++c) {
            ulonglong2 a = __ldg(q0 + c); w0[2 * c] = a.x; w0[2 * c + 1] = a.y;
            ulonglong2 b = __ldg(q1 + c); w1[2 * c] = b.x; w1[2 * c + 1] = b.y;
            ulonglong2 cc = __ldg(q2 + c); w2[2 * c] = cc.x; w2[2 * c + 1] = cc.y;
            ulonglong2 d = __ldg(q3 + c); w3[2 * c] = d.x; w3[2 * c + 1] = d.y;
        }
    }
    const u64 hb0 = pk(__ldg(&b1[r]),      0.0f);
    const u64 hb1 = pk(__ldg(&b1[r + 8]),  0.0f);
    const u64 hb2 = pk(__ldg(&b1[r + 16]), 0.0f);
    const u64 hb3 = pk(__ldg(&b1[r + 24]), 0.0f);

    // layer-2 lane roles: lanes 0..19 -> (elem me, output-pair jj); 20..31 mirror
    const int jj = lid % 5;
    const int me = (lid / 5) & 3;
    const u64 b2p = pk(__ldg(&b2[2 * jj]), __ldg(&b2[2 * jj + 1]));
    const float* lj = g_lut + 2 * jj;
    const u32 sel = (u32)me | (((u32)me + 4) << 4);   // byte_perm: byte 'me' of a,b

    __syncthreads();

    // ================= software-pipelined main recurrence (rolled) ================
    const float* xbase = smx + eLocal * IMG;

    float m0 = 0.0f, m1 = 0.0f, m2 = 0.0f, m3 = 0.0f;   // membranes (scalar units)
    u64 v2p = 0ull;
    int ac0 = 0, ac1 = 0;            // integer spike counters (exact)
    float h0c, h1c, h2c, h3c;
    COMPUTE_H(0, h0c, h1c, h2c, h3c);          // prologue: h for t=0

#pragma unroll 2
    for (int t = 0; t < 28; ++t) {
        // ---- IF layer 1 (scalar) + spike ballots ----
        m0 += h0c; m1 += h1c; m2 += h2c; m3 += h3c;
        bool s0 = (m0 >= 1.0f);      // unit r
        bool s1 = (m1 >= 1.0f);      // unit r+8
        bool s2 = (m2 >= 1.0f);      // unit r+16
        bool s3 = (m3 >= 1.0f);      // unit r+24
        u32 B0 = __ballot_sync(0xffffffffu, s0);
        u32 B1 = __ballot_sync(0xffffffffu, s1);
        u32 B2 = __ballot_sync(0xffffffffu, s2);
        u32 B3 = __ballot_sync(0xffffffffu, s3);
        m0 = s0 ? 0.0f : m0;
        m1 = s1 ? 0.0f : m1;
        m2 = s2 ? 0.0f : m2;
        m3 = s3 ? 0.0f : m3;

        // ---- 32-bit spike mask of elem 'me' via 3 PRMTs (bit k = unit k) ----
        u32 lo16 = __byte_perm(B0, B1, sel);
        u32 hi16 = __byte_perm(B2, B3, sel);
        u32 M    = __byte_perm(lo16, hi16, 0x5410);

        // ---- issue 4 byte-LUT LDGs now (L1D-resident table, 8B each) ----
        u64 l0 = __ldg(reinterpret_cast<const u64*>(lj + (M & 255u) * 10));
        u64 l1 = __ldg(reinterpret_cast<const u64*>(lj + ((M >> 8)  & 255u) * 10 + 2560));
        u64 l2 = __ldg(reinterpret_cast<const u64*>(lj + ((M >> 16) & 255u) * 10 + 5120));
        u64 l3 = __ldg(reinterpret_cast<const u64*>(lj + (M >> 24) * 10 + 7680));

        // ---- overlap: h for t+1 (t=27 prefetch discarded; in-bounds smem) ----
        float h0n, h1n, h2n, h3n;
        COMPUTE_H(t + 1, h0n, h1n, h2n, h3n);

        // ---- layer 2: consume LUT (b2-first, ascending p4: exact R13 order) ----
        u64 h2 = b2p;
        h2 = add2(h2, l0); h2 = add2(h2, l1); h2 = add2(h2, l2); h2 = add2(h2, l3);

        // ---- IF layer 2 + integer rate accumulation ----
        v2p = add2(v2p, h2);
        float g0, g1; upk(g0, g1, v2p);
        bool t0 = (g0 >= 1.0f), t1 = (g1 >= 1.0f);
        ac0 += t0; ac1 += t1;
        v2p = pk(t0 ? 0.0f : g0, t1 ? 0.0f : g1);

        h0c = h0n; h1c = h1n; h2c = h2n; h3c = h3n;
    }

    // ---- output: lanes 0..19 write their (elem, j-pair) firing rates ----
    int ge = gbase + wid * EPW + me;
    if (lid < 20 && ge < B) {
        *reinterpret_cast<float2*>(out + (size_t)ge * 10 + 2 * jj) =
            make_float2((float)ac0 * (1.0f / 28.0f), (float)ac1 * (1.0f / 28.0f));
    }
}

extern "C" void kernel_launch(void* const* d_in, const int* in_sizes, int n_in,
                              void* d_out, int out_size) {
    const float* x  = (const float*)d_in[0];
    const float* W1 = (const float*)d_in[1];
    const float* b1 = (const float*)d_in[2];
    const float* W2 = (const float*)d_in[3];
    const float* b2 = (const float*)d_in[4];
    float* out = (float*)d_out;

    int B = in_sizes[0] / 784;
    int smem = SMEMW * (int)sizeof(float);   // ~58.1 KB -> 3 blocks/SM (12 warps)

    cudaFuncSetAttribute(snn_kernel, cudaFuncAttributeMaxDynamicSharedMemorySize, smem);

    build_lut<<<40, 256>>>(W2);               // 10240 entries, one per thread

    int grid = (B + EPB - 1) / EPB;
    snn_kernel<<<grid, TPB, smem>>>(x, W1, b1, W2, b2, out, B);
}